// round 2
// baseline (speedup 1.0000x reference)
#include <cuda_runtime.h>
#include <cuda_bf16.h>
#include <cstdint>
#include <cstddef>

// Problem dims (fixed)
#define B_   4
#define S_   4096
#define D_   1024
#define QK_  128
#define H_   2048
#define NBROWS (B_ * S_)   // 16384

// ------------------------- device scratch (static, no allocation) -------------
__device__ unsigned char g_normed8[(size_t)NBROWS * D_];     // x1
__device__ unsigned char g_WhT8 [(size_t)2 * H_ * D_];       // x32, [2H][D]
__device__ unsigned char g_WqkT8[(size_t)QK_ * D_];          // x32, [QK][D]
__device__ unsigned char g_WoT8 [(size_t)D_ * H_];           // x32, [D][H]
__device__ unsigned char g_q8 [(size_t)NBROWS * QK_];        // x64
__device__ unsigned char g_k8 [(size_t)NBROWS * QK_];        // x64
__device__ unsigned char g_a8 [(size_t)B_ * S_ * S_];        // attn x 2^24
__device__ unsigned char g_vT8[(size_t)B_ * H_ * S_];        // v x8, [b][H][S]
__device__ unsigned char g_og8[(size_t)NBROWS * H_];         // og x 2^16
__device__ __nv_bfloat16 g_gate[(size_t)NBROWS * H_];
__device__ float g_bias_lut[2 * S_ - 1];

__device__ __forceinline__ uint16_t pack_e4m3(float lo, float hi) {
    uint16_t r;
    asm("cvt.rn.satfinite.e4m3x2.f32 %0, %1, %2;" : "=h"(r) : "f"(hi), "f"(lo));
    return r;
}
__device__ __forceinline__ float siluf(float z) { return z / (1.0f + __expf(-z)); }

// ------------------------- prep: rel-bias LUT ---------------------------------
__global__ void lut_kernel(const float* __restrict__ rel_emb)
{
    int i = blockIdx.x * blockDim.x + threadIdx.x;
    if (i >= 2 * S_ - 1) return;
    int d = i - (S_ - 1);
    int n = -d;
    int ret = (n < 0) ? 16 : 0;
    int na = n < 0 ? -n : n;
    int b;
    if (na < 8) b = na;
    else {
        float v = logf((float)na / 8.0f) / logf(16.0f) * 8.0f;
        int vi = 8 + (int)v;
        b = vi < 15 ? vi : 15;
    }
    g_bias_lut[i] = rel_emb[ret + b] * 32.0f;   // scale = sqrt(D)
}

// ------------------------- prep: transpose+convert weights (x32 -> fp8) -------
__global__ void wtrans_kernel(const float* __restrict__ src,
                              unsigned char* __restrict__ dst, int R, int C)
{
    __shared__ float t[32][33];
    int c0 = blockIdx.x * 32, r0 = blockIdx.y * 32;
    #pragma unroll
    for (int i = 0; i < 32; i += 8)
        t[threadIdx.y + i][threadIdx.x] =
            src[(size_t)(r0 + threadIdx.y + i) * C + c0 + threadIdx.x];
    __syncthreads();
    #pragma unroll
    for (int i = 0; i < 32; i += 8) {
        float v = t[threadIdx.x][threadIdx.y + i] * 32.0f;
        dst[(size_t)(c0 + threadIdx.y + i) * R + r0 + threadIdx.x] =
            (unsigned char)(pack_e4m3(v, v) & 0xFF);
    }
}

// ------------------------- LayerNorm: x -> normed (fp8) -----------------------
__global__ void ln_kernel(const float* __restrict__ x,
                          const float* __restrict__ gamma,
                          const float* __restrict__ beta)
{
    int row = blockIdx.x;
    const float4* xr = reinterpret_cast<const float4*>(x + (size_t)row * D_);
    float4 v = xr[threadIdx.x];                 // 256 threads * 4 = 1024
    float s  = v.x + v.y + v.z + v.w;
    float ss = fmaf(v.x, v.x, fmaf(v.y, v.y, fmaf(v.z, v.z, v.w * v.w)));
    #pragma unroll
    for (int o = 16; o; o >>= 1) {
        s  += __shfl_xor_sync(0xFFFFFFFFu, s,  o);
        ss += __shfl_xor_sync(0xFFFFFFFFu, ss, o);
    }
    __shared__ float sh[2][8];
    int lane = threadIdx.x & 31, w = threadIdx.x >> 5;
    if (lane == 0) { sh[0][w] = s; sh[1][w] = ss; }
    __syncthreads();
    if (threadIdx.x < 32) {
        float a = (threadIdx.x < 8) ? sh[0][threadIdx.x] : 0.f;
        float b = (threadIdx.x < 8) ? sh[1][threadIdx.x] : 0.f;
        #pragma unroll
        for (int o = 4; o; o >>= 1) {
            a += __shfl_xor_sync(0xFFFFFFFFu, a, o);
            b += __shfl_xor_sync(0xFFFFFFFFu, b, o);
        }
        if (threadIdx.x == 0) { sh[0][0] = a; sh[1][0] = b; }
    }
    __syncthreads();
    float mean = sh[0][0] * (1.0f / D_);
    float var  = sh[1][0] * (1.0f / D_) - mean * mean;
    float r = rsqrtf(var + 1e-5f);
    int c = threadIdx.x * 4;
    float y0 = (v.x - mean) * r * gamma[c + 0] + beta[c + 0];
    float y1 = (v.y - mean) * r * gamma[c + 1] + beta[c + 1];
    float y2 = (v.z - mean) * r * gamma[c + 2] + beta[c + 2];
    float y3 = (v.w - mean) * r * gamma[c + 3] + beta[c + 3];
    uint32_t wrd = (uint32_t)pack_e4m3(y0, y1) | ((uint32_t)pack_e4m3(y2, y3) << 16);
    reinterpret_cast<uint32_t*>(g_normed8 + (size_t)row * D_)[threadIdx.x] = wrd;
}

// ------------------------- generic fp8 tensor-core GEMM -----------------------
// C[M,N] = A[M,K] * B[N,K]^T ; both operands e4m3, K-contiguous, K multiple of 64.
#define PITCH 80                     // bytes per smem row (64 data + 16 pad)
#define ABYTES (128 * PITCH)         // 10240
#define STAGE_BYTES (2 * ABYTES)     // 20480
#define NSTAGE 3
#define SMEM_BYTES (NSTAGE * STAGE_BYTES)  // 61440

#define CP16(dst, src) \
    asm volatile("cp.async.cg.shared.global [%0], [%1], 16;\n" :: "r"(dst), "l"(src))

// EPI: 0=hidden(silu-> vT fp8 / gate bf16)  1=qk(silu->q8,k8)
//      2=sim(bias,relu^2 -> a8)  3=av(*gate -> og8)  4=out(+bo+x -> d_out f32)
template<int EPI, int Kc>
__global__ void __launch_bounds__(256)
gemm8(const float* __restrict__ p0, const float* __restrict__ p1,
      const float* __restrict__ p2, float* __restrict__ pout)
{
    extern __shared__ unsigned char sm[];
    const int tid = threadIdx.x, lane = tid & 31, warp = tid >> 5;
    const int warp_m = (warp >> 1) * 32;
    const int warp_n = (warp & 1) * 64;
    const int bm = blockIdx.y * 128;
    const int bn = blockIdx.x * 128;
    const int z  = blockIdx.z;

    const unsigned char *A, *Bg;
    if constexpr (EPI == 0)      { A = g_normed8; Bg = g_WhT8; }
    else if constexpr (EPI == 1) { A = g_normed8; Bg = g_WqkT8; }
    else if constexpr (EPI == 2) { A = g_q8 + (size_t)z * S_ * QK_;
                                   Bg = g_k8 + (size_t)z * S_ * QK_; }
    else if constexpr (EPI == 3) { A = g_a8  + (size_t)z * S_ * S_;
                                   Bg = g_vT8 + (size_t)z * H_ * S_; }
    else                         { A = g_og8; Bg = g_WoT8; }

    // gmem->smem: each thread copies 2x16B for A and B per stage
    const int tr = tid >> 2;               // 0..63
    const int tc = (tid & 3) * 16;         // byte col within 64
    const unsigned char* a0 = A  + (size_t)(bm + tr) * Kc + tc;
    const unsigned char* a1 = a0 + (size_t)64 * Kc;
    const unsigned char* b0 = Bg + (size_t)(bn + tr) * Kc + tc;
    const unsigned char* b1 = b0 + (size_t)64 * Kc;

    const uint32_t smem_u = (uint32_t)__cvta_generic_to_shared(sm);
    const uint32_t dA0 = smem_u + tr * PITCH + tc;
    const uint32_t dA1 = dA0 + 64 * PITCH;
    const uint32_t dB0 = dA0 + ABYTES;
    const uint32_t dB1 = dB0 + 64 * PITCH;

    // ldmatrix lane addressing (non-trans, fp8 viewed as b16)
    const int lrow  = (lane & 7) + ((lane >> 3) & 1) * 8;
    const int lhalf = lane >> 4;
    const uint32_t lmA = smem_u + (warp_m + lrow) * PITCH + lhalf * 16;
    const uint32_t lmB = smem_u + ABYTES + (warp_n + lrow) * PITCH + lhalf * 16;

    const int KT = Kc / 64;
    #pragma unroll
    for (int s = 0; s < NSTAGE - 1; ++s) {
        if (s < KT) {
            uint32_t o = s * STAGE_BYTES;
            size_t  ko = (size_t)s * 64;
            CP16(dA0 + o, a0 + ko); CP16(dA1 + o, a1 + ko);
            CP16(dB0 + o, b0 + ko); CP16(dB1 + o, b1 + ko);
        }
        asm volatile("cp.async.commit_group;\n");
    }

    float c[2][8][4] = {};

    for (int kt = 0; kt < KT; ++kt) {
        asm volatile("cp.async.wait_group 1;\n");
        __syncthreads();
        {
            int pf = kt + NSTAGE - 1;
            if (pf < KT) {
                uint32_t o = (uint32_t)(pf % NSTAGE) * STAGE_BYTES;
                size_t  ko = (size_t)pf * 64;
                CP16(dA0 + o, a0 + ko); CP16(dA1 + o, a1 + ko);
                CP16(dB0 + o, b0 + ko); CP16(dB1 + o, b1 + ko);
            }
            asm volatile("cp.async.commit_group;\n");
        }
        const uint32_t bufo = (uint32_t)(kt % NSTAGE) * STAGE_BYTES;
        #pragma unroll
        for (int s = 0; s < 2; ++s) {        // two k32 steps per 64B stage
            uint32_t af[2][4];
            #pragma unroll
            for (int mf = 0; mf < 2; ++mf) {
                uint32_t addr = lmA + bufo + mf * (16 * PITCH) + s * 32;
                asm volatile("ldmatrix.sync.aligned.m8n8.x4.shared.b16 {%0,%1,%2,%3},[%4];"
                    : "=r"(af[mf][0]), "=r"(af[mf][1]), "=r"(af[mf][2]), "=r"(af[mf][3])
                    : "r"(addr));
            }
            uint32_t bfm[8][2];
            #pragma unroll
            for (int nq = 0; nq < 4; ++nq) {
                uint32_t addr = lmB + bufo + nq * (16 * PITCH) + s * 32;
                uint32_t r0, r1, r2, r3;
                asm volatile("ldmatrix.sync.aligned.m8n8.x4.shared.b16 {%0,%1,%2,%3},[%4];"
                    : "=r"(r0), "=r"(r1), "=r"(r2), "=r"(r3) : "r"(addr));
                bfm[nq*2  ][0] = r0; bfm[nq*2  ][1] = r2;
                bfm[nq*2+1][0] = r1; bfm[nq*2+1][1] = r3;
            }
            #pragma unroll
            for (int mf = 0; mf < 2; ++mf)
            #pragma unroll
            for (int nf = 0; nf < 8; ++nf)
                asm volatile(
                    "mma.sync.aligned.m16n8k32.row.col.f32.e4m3.e4m3.f32 "
                    "{%0,%1,%2,%3},{%4,%5,%6,%7},{%8,%9},{%0,%1,%2,%3};"
                    : "+f"(c[mf][nf][0]), "+f"(c[mf][nf][1]),
                      "+f"(c[mf][nf][2]), "+f"(c[mf][nf][3])
                    : "r"(af[mf][0]), "r"(af[mf][1]), "r"(af[mf][2]), "r"(af[mf][3]),
                      "r"(bfm[nf][0]), "r"(bfm[nf][1]));
        }
    }

    // ------------------------------ epilogues ---------------------------------
    const int er = bm + warp_m + (lane >> 2);
    const int ec = bn + warp_n + (lane & 3) * 2;

    if constexpr (EPI == 0) {
        if (bn < H_) {
            // v tile: silu, scale x8, fp8, transpose via smem -> g_vT8[b][h][s]
            __syncthreads();
            #pragma unroll
            for (int mf = 0; mf < 2; ++mf)
            #pragma unroll
            for (int nf = 0; nf < 8; ++nf) {
                const int rl = warp_m + (lane >> 2) + mf * 16;
                const int cl = warp_n + (lane & 3) * 2 + nf * 8;
                #pragma unroll
                for (int e = 0; e < 4; ++e) {
                    int r  = rl + ((e >> 1) << 3);
                    int cc = cl + (e & 1);
                    float zf = c[mf][nf][e] * (1.0f / 32.0f) + p0[bn + cc];
                    float sv = siluf(zf) * 8.0f;
                    sm[cc * 132 + r] = (unsigned char)(pack_e4m3(sv, sv) & 0xFF);
                }
            }
            __syncthreads();
            const int b  = bm >> 12;
            const int s0 = bm & (S_ - 1);
            #pragma unroll
            for (int i = 0; i < 16; ++i) {
                int h = warp * 16 + i;
                uint32_t vv = *reinterpret_cast<const uint32_t*>(sm + h * 132 + lane * 4);
                *reinterpret_cast<uint32_t*>(
                    g_vT8 + ((size_t)b * H_ + bn + h) * S_ + s0 + lane * 4) = vv;
            }
        } else {
            // gate tile: silu -> bf16 row-major
            #pragma unroll
            for (int mf = 0; mf < 2; ++mf)
            #pragma unroll
            for (int nf = 0; nf < 8; ++nf) {
                const int col = ec + nf * 8;
                const float bb0 = p0[col], bb1 = p0[col + 1];
                #pragma unroll
                for (int half = 0; half < 2; ++half) {
                    const int row = er + mf * 16 + half * 8;
                    float z0 = c[mf][nf][half * 2 + 0] * (1.0f / 32.0f) + bb0;
                    float z1 = c[mf][nf][half * 2 + 1] * (1.0f / 32.0f) + bb1;
                    __nv_bfloat162 h2;
                    h2.x = __float2bfloat16(siluf(z0));
                    h2.y = __float2bfloat16(siluf(z1));
                    *reinterpret_cast<__nv_bfloat162*>(
                        &g_gate[(size_t)row * H_ + (col - H_)]) = h2;
                }
            }
        }
    } else if constexpr (EPI == 1) {
        #pragma unroll
        for (int mf = 0; mf < 2; ++mf)
        #pragma unroll
        for (int nf = 0; nf < 8; ++nf) {
            const int col = ec + nf * 8;
            const float bb0 = p0[col], bb1 = p0[col + 1];
            const float g0 = p1[col], g1 = p1[col + 1];
            const float gk0 = p1[QK_ + col], gk1 = p1[QK_ + col + 1];
            const float b0f = p2[col], b1f = p2[col + 1];
            const float bk0 = p2[QK_ + col], bk1 = p2[QK_ + col + 1];
            #pragma unroll
            for (int half = 0; half < 2; ++half) {
                const int row = er + mf * 16 + half * 8;
                float sv0 = siluf(c[mf][nf][half * 2 + 0] * (1.0f / 32.0f) + bb0);
                float sv1 = siluf(c[mf][nf][half * 2 + 1] * (1.0f / 32.0f) + bb1);
                float q0 = (sv0 * g0 + b0f) * 64.0f, q1 = (sv1 * g1 + b1f) * 64.0f;
                float k0 = (sv0 * gk0 + bk0) * 64.0f, k1 = (sv1 * gk1 + bk1) * 64.0f;
                *reinterpret_cast<uint16_t*>(&g_q8[(size_t)row * QK_ + col]) = pack_e4m3(q0, q1);
                *reinterpret_cast<uint16_t*>(&g_k8[(size_t)row * QK_ + col]) = pack_e4m3(k0, k1);
            }
        }
    } else if constexpr (EPI == 2) {
        unsigned char* dst = g_a8 + (size_t)z * S_ * S_;
        #pragma unroll
        for (int mf = 0; mf < 2; ++mf)
        #pragma unroll
        for (int nf = 0; nf < 8; ++nf) {
            const int col = ec + nf * 8;
            #pragma unroll
            for (int half = 0; half < 2; ++half) {
                const int row = er + mf * 16 + half * 8;
                float l0 = g_bias_lut[col - row + (S_ - 1)];
                float l1 = g_bias_lut[col + 1 - row + (S_ - 1)];
                // stored = (4096*t)^2 = t^2 * 2^24 ; t = relu((sim+bias)/4096)
                float t0 = fmaxf(fmaf(c[mf][nf][half * 2 + 0], 1.0f / 4096.0f, l0), 0.0f);
                float t1 = fmaxf(fmaf(c[mf][nf][half * 2 + 1], 1.0f / 4096.0f, l1), 0.0f);
                *reinterpret_cast<uint16_t*>(&dst[(size_t)row * S_ + col]) =
                    pack_e4m3(t0 * t0, t1 * t1);
            }
        }
    } else if constexpr (EPI == 3) {
        #pragma unroll
        for (int mf = 0; mf < 2; ++mf)
        #pragma unroll
        for (int nf = 0; nf < 8; ++nf) {
            const int col = ec + nf * 8;
            #pragma unroll
            for (int half = 0; half < 2; ++half) {
                const int row = er + mf * 16 + half * 8;
                const size_t grow = (size_t)z * S_ + row;
                __nv_bfloat162 gv = *reinterpret_cast<const __nv_bfloat162*>(
                    &g_gate[grow * H_ + col]);
                // og8 = acc * gate * 2^-27 * 2^16 = acc*gate/2048
                float o0 = c[mf][nf][half * 2 + 0] * __bfloat162float(gv.x) * (1.0f / 2048.0f);
                float o1 = c[mf][nf][half * 2 + 1] * __bfloat162float(gv.y) * (1.0f / 2048.0f);
                *reinterpret_cast<uint16_t*>(&g_og8[grow * H_ + col]) = pack_e4m3(o0, o1);
            }
        }
    } else {
        #pragma unroll
        for (int mf = 0; mf < 2; ++mf)
        #pragma unroll
        for (int nf = 0; nf < 8; ++nf) {
            const int col = ec + nf * 8;
            const float bb0 = p0[col], bb1 = p0[col + 1];
            #pragma unroll
            for (int half = 0; half < 2; ++half) {
                const int row = er + mf * 16 + half * 8;
                const size_t idx = (size_t)row * D_ + col;
                float2 o;
                o.x = c[mf][nf][half * 2 + 0] * (1.0f / 2097152.0f) + bb0 + p1[idx];
                o.y = c[mf][nf][half * 2 + 1] * (1.0f / 2097152.0f) + bb1 + p1[idx + 1];
                *reinterpret_cast<float2*>(&pout[idx]) = o;
            }
        }
    }
}

// ------------------------------- launch ---------------------------------------
extern "C" void kernel_launch(void* const* d_in, const int* in_sizes, int n_in,
                              void* d_out, int out_size)
{
    const float* x    = (const float*)d_in[0];
    const float* ln_g = (const float*)d_in[1];
    const float* ln_b = (const float*)d_in[2];
    const float* Wh   = (const float*)d_in[3];
    const float* bh   = (const float*)d_in[4];
    const float* Wqk  = (const float*)d_in[5];
    const float* bqk  = (const float*)d_in[6];
    const float* osg  = (const float*)d_in[7];
    const float* osb  = (const float*)d_in[8];
    const float* Wo   = (const float*)d_in[9];
    const float* bo   = (const float*)d_in[10];
    const float* rel  = (const float*)d_in[11];
    float* out = (float*)d_out;

    static bool attr_done = false;
    if (!attr_done) {
        cudaFuncSetAttribute(gemm8<0, 1024>, cudaFuncAttributeMaxDynamicSharedMemorySize, SMEM_BYTES);
        cudaFuncSetAttribute(gemm8<1, 1024>, cudaFuncAttributeMaxDynamicSharedMemorySize, SMEM_BYTES);
        cudaFuncSetAttribute(gemm8<2, 128>,  cudaFuncAttributeMaxDynamicSharedMemorySize, SMEM_BYTES);
        cudaFuncSetAttribute(gemm8<3, 4096>, cudaFuncAttributeMaxDynamicSharedMemorySize, SMEM_BYTES);
        cudaFuncSetAttribute(gemm8<4, 2048>, cudaFuncAttributeMaxDynamicSharedMemorySize, SMEM_BYTES);
        attr_done = true;
    }

    // weight transposes (+x32 fp8) and bias LUT
    unsigned char* dWhT;  cudaGetSymbolAddress((void**)&dWhT,  g_WhT8);
    unsigned char* dWqkT; cudaGetSymbolAddress((void**)&dWqkT, g_WqkT8);
    unsigned char* dWoT;  cudaGetSymbolAddress((void**)&dWoT,  g_WoT8);
    wtrans_kernel<<<dim3((2 * H_) / 32, D_ / 32), dim3(32, 8)>>>(Wh,  dWhT,  D_, 2 * H_);
    wtrans_kernel<<<dim3(QK_ / 32,     D_ / 32), dim3(32, 8)>>>(Wqk, dWqkT, D_, QK_);
    wtrans_kernel<<<dim3(D_ / 32,      H_ / 32), dim3(32, 8)>>>(Wo,  dWoT,  H_, D_);
    lut_kernel<<<(2 * S_ - 1 + 255) / 256, 256>>>(rel);
    ln_kernel<<<NBROWS, 256>>>(x, ln_g, ln_b);

    // hidden = silu(normed @ Wh + bh) -> vT(fp8), gate(bf16)
    gemm8<0, 1024><<<dim3((2 * H_) / 128, NBROWS / 128), 256, SMEM_BYTES>>>(bh, nullptr, nullptr, nullptr);
    // qk = silu(normed @ Wqk + bqk) -> q8, k8
    gemm8<1, 1024><<<dim3(1, NBROWS / 128), 256, SMEM_BYTES>>>(bqk, osg, osb, nullptr);
    // a8 = (4096*relu((q k^T + bias)/4096))^2 (per batch)
    gemm8<2, 128><<<dim3(S_ / 128, S_ / 128, B_), 256, SMEM_BYTES>>>(nullptr, nullptr, nullptr, nullptr);
    // og8 = (a @ v) * gate (per batch, rescaled)
    gemm8<3, 4096><<<dim3(H_ / 128, S_ / 128, B_), 256, SMEM_BYTES>>>(nullptr, nullptr, nullptr, nullptr);
    // out = og @ Wo + bo + x
    gemm8<4, 2048><<<dim3(D_ / 128, NBROWS / 128), 256, SMEM_BYTES>>>(bo, x, nullptr, out);
}

// round 4
// speedup vs baseline: 1.2193x; 1.2193x over previous
#include <cuda_runtime.h>
#include <cuda_bf16.h>
#include <cstdint>
#include <cstddef>

// Problem dims (fixed)
#define B_   4
#define S_   4096
#define D_   1024
#define QK_  128
#define H_   2048
#define NBROWS (B_ * S_)   // 16384

// ------------------------- device scratch (static, no allocation) -------------
__device__ __nv_bfloat16 g_normed[(size_t)NBROWS * D_];
__device__ __nv_bfloat16 g_Wh [(size_t)D_ * 2 * H_];
__device__ __nv_bfloat16 g_Wqk[(size_t)D_ * QK_];
__device__ __nv_bfloat16 g_Wo [(size_t)H_ * D_];
__device__ __nv_bfloat16 g_v   [(size_t)NBROWS * H_];
__device__ __nv_bfloat16 g_gate[(size_t)NBROWS * H_];
__device__ __nv_bfloat16 g_q   [(size_t)NBROWS * QK_];
__device__ __nv_bfloat16 g_kT  [(size_t)B_ * QK_ * S_];
__device__ __nv_bfloat16 g_attn[(size_t)B_ * S_ * S_];
__device__ __nv_bfloat16 g_og  [(size_t)NBROWS * H_];
__device__ float g_bias_lut[2 * S_ - 1];

// ------------------------- prep: weight conversion + rel-bias LUT -------------
__global__ void prep_kernel(const float* __restrict__ Wh,
                            const float* __restrict__ Wqk,
                            const float* __restrict__ Wo,
                            const float* __restrict__ rel_emb)
{
    int i = blockIdx.x * blockDim.x + threadIdx.x;
    const int nWh  = D_ * 2 * H_;
    const int nWqk = D_ * QK_;
    const int nWo  = H_ * D_;
    if (i < nWh) { g_Wh[i] = __float2bfloat16(Wh[i]); return; }
    i -= nWh;
    if (i < nWqk) { g_Wqk[i] = __float2bfloat16(Wqk[i]); return; }
    i -= nWqk;
    if (i < nWo) { g_Wo[i] = __float2bfloat16(Wo[i]); return; }
    i -= nWo;
    if (i < 2 * S_ - 1) {
        int d = i - (S_ - 1);
        int n = -d;
        int ret = (n < 0) ? 16 : 0;
        int na = n < 0 ? -n : n;
        int b;
        if (na < 8) b = na;
        else {
            float v = logf((float)na / 8.0f) / logf(16.0f) * 8.0f;
            int vi = 8 + (int)v;
            b = vi < 15 ? vi : 15;
        }
        g_bias_lut[i] = rel_emb[ret + b] * 32.0f;  // scale = sqrt(D)
    }
}

// ------------------------- LayerNorm: x -> normed (bf16) ----------------------
__global__ void ln_kernel(const float* __restrict__ x,
                          const float* __restrict__ gamma,
                          const float* __restrict__ beta)
{
    int row = blockIdx.x;
    const float4* xr = reinterpret_cast<const float4*>(x + (size_t)row * D_);
    float4 v = xr[threadIdx.x];
    float s  = v.x + v.y + v.z + v.w;
    float ss = fmaf(v.x, v.x, fmaf(v.y, v.y, fmaf(v.z, v.z, v.w * v.w)));
    #pragma unroll
    for (int o = 16; o; o >>= 1) {
        s  += __shfl_xor_sync(0xFFFFFFFFu, s,  o);
        ss += __shfl_xor_sync(0xFFFFFFFFu, ss, o);
    }
    __shared__ float sh[2][8];
    int lane = threadIdx.x & 31, w = threadIdx.x >> 5;
    if (lane == 0) { sh[0][w] = s; sh[1][w] = ss; }
    __syncthreads();
    if (threadIdx.x < 32) {
        float a = (threadIdx.x < 8) ? sh[0][threadIdx.x] : 0.f;
        float b = (threadIdx.x < 8) ? sh[1][threadIdx.x] : 0.f;
        #pragma unroll
        for (int o = 4; o; o >>= 1) {
            a += __shfl_xor_sync(0xFFFFFFFFu, a, o);
            b += __shfl_xor_sync(0xFFFFFFFFu, b, o);
        }
        if (threadIdx.x == 0) { sh[0][0] = a; sh[1][0] = b; }
    }
    __syncthreads();
    float mean = sh[0][0] * (1.0f / D_);
    float var  = sh[1][0] * (1.0f / D_) - mean * mean;
    float r = rsqrtf(var + 1e-5f);
    int c = threadIdx.x * 4;
    __nv_bfloat16* o = g_normed + (size_t)row * D_;
    o[c + 0] = __float2bfloat16((v.x - mean) * r * gamma[c + 0] + beta[c + 0]);
    o[c + 1] = __float2bfloat16((v.y - mean) * r * gamma[c + 1] + beta[c + 1]);
    o[c + 2] = __float2bfloat16((v.z - mean) * r * gamma[c + 2] + beta[c + 2]);
    o[c + 3] = __float2bfloat16((v.w - mean) * r * gamma[c + 3] + beta[c + 3]);
}

// ------------------------- generic bf16 tensor-core GEMM ----------------------
// CTA tile 128x128, 4 warps (128 thr), warp tile 64x64, 4-stage cp.async.
#define BM 128
#define BN 128
#define BK 32
#define NSTAGE 4
#define LDA_S 40    // elements (80 B pitch)  -> conflict-free ldmatrix
#define LDB_S 136   // elements (272 B pitch)
#define ASTAGE_B (BM * LDA_S * 2)          // 10240
#define BSTAGE_B (BK * LDB_S * 2)          // 8704
#define STAGE_B  (ASTAGE_B + BSTAGE_B)     // 18944
#define SMEM_B   (NSTAGE * STAGE_B)        // 75776

__device__ __forceinline__ uint32_t s2u(const void* p) {
    return (uint32_t)__cvta_generic_to_shared(p);
}
#define CP16(dst, src) \
    asm volatile("cp.async.cg.shared.global [%0], [%1], 16;\n" :: "r"(dst), "l"(src))

// EPI: 0=hidden(silu->v/gate) 1=qk(silu->q,kT) 2=sim(bias,relu^2->attn)
//      3=av(*gate->og) 4=out(+bo+x->f32)
template<int EPI, int Kc, int Nc>
__global__ void __launch_bounds__(128, 2)
gemm4(const float* __restrict__ p0, const float* __restrict__ p1,
      const float* __restrict__ p2, float* __restrict__ pout)
{
    extern __shared__ unsigned char smraw[];
    const uint32_t smu = s2u(smraw);

    const int tid  = threadIdx.x;
    const int lane = tid & 31;
    const int warp = tid >> 5;
    const int warp_m = (warp >> 1) * 64;
    const int warp_n = (warp & 1) * 64;
    const int bm = blockIdx.y * BM;
    const int bn = blockIdx.x * BN;
    const int z  = blockIdx.z;

    const __nv_bfloat16 *A, *Bg;
    if constexpr (EPI == 0)      { A = g_normed; Bg = g_Wh; }
    else if constexpr (EPI == 1) { A = g_normed; Bg = g_Wqk; }
    else if constexpr (EPI == 2) { A = g_q   + (size_t)z * S_ * QK_;
                                   Bg = g_kT + (size_t)z * QK_ * S_; }
    else if constexpr (EPI == 3) { A = g_attn + (size_t)z * S_ * S_;
                                   Bg = g_v   + (size_t)z * S_ * H_; }
    else                         { A = g_og; Bg = g_Wo; }

    // gmem->smem tiling: A 128x32 (512 x16B chunks), B 32x128 (512 chunks), 128 thr
    const int arow = tid >> 2;            // 0..31 (+32*i)
    const int acol = (tid & 3) * 8;       // k offset (elems)
    const int brow = tid >> 4;            // 0..7 (+8*i)
    const int bcol = (tid & 15) * 8;      // n offset (elems)

    const __nv_bfloat16* a_src = A  + (size_t)(bm + arow) * Kc + acol;
    const __nv_bfloat16* b_src = Bg + (size_t)brow * Nc + bn + bcol;
    const uint32_t a_dst = smu + arow * (LDA_S * 2) + acol * 2;
    const uint32_t b_dst = smu + ASTAGE_B + brow * (LDB_S * 2) + bcol * 2;

    // ldmatrix per-lane addressing (same proven formula as R1)
    const int q8    = lane >> 3;
    const int lrow  = (lane & 7) + (q8 & 1) * 8;
    const int lcol8 = (q8 >> 1) * 8;
    const uint32_t a_lm = smu + (warp_m + lrow) * (LDA_S * 2) + lcol8 * 2;
    const uint32_t b_lm = smu + ASTAGE_B + lrow * (LDB_S * 2) + (warp_n + lcol8) * 2;

    const int KT = Kc / BK;

    // prologue: stages 0..NSTAGE-2
    #pragma unroll
    for (int s = 0; s < NSTAGE - 1; ++s) {
        if (s < KT) {
            const uint32_t so = s * STAGE_B;
            #pragma unroll
            for (int i = 0; i < 4; ++i)
                CP16(a_dst + so + i * 32 * (LDA_S * 2),
                     a_src + (size_t)s * BK + (size_t)i * 32 * Kc);
            #pragma unroll
            for (int i = 0; i < 4; ++i)
                CP16(b_dst + so + i * 8 * (LDB_S * 2),
                     b_src + (size_t)s * BK * Nc + (size_t)i * 8 * Nc);
        }
        asm volatile("cp.async.commit_group;\n");
    }

    float c[4][8][4] = {};

    for (int kt = 0; kt < KT; ++kt) {
        asm volatile("cp.async.wait_group %0;\n" :: "n"(NSTAGE - 2));
        __syncthreads();
        {
            const int pf = kt + NSTAGE - 1;
            if (pf < KT) {
                const uint32_t so = (pf % NSTAGE) * STAGE_B;
                #pragma unroll
                for (int i = 0; i < 4; ++i)
                    CP16(a_dst + so + i * 32 * (LDA_S * 2),
                         a_src + (size_t)pf * BK + (size_t)i * 32 * Kc);
                #pragma unroll
                for (int i = 0; i < 4; ++i)
                    CP16(b_dst + so + i * 8 * (LDB_S * 2),
                         b_src + (size_t)pf * BK * Nc + (size_t)i * 8 * Nc);
            }
            asm volatile("cp.async.commit_group;\n");
        }
        const uint32_t bufo = (kt % NSTAGE) * STAGE_B;
        #pragma unroll
        for (int s = 0; s < 2; ++s) {          // two k16 steps per BK
            uint32_t a[4][4];
            #pragma unroll
            for (int mf = 0; mf < 4; ++mf) {
                uint32_t addr = a_lm + bufo + mf * (16 * LDA_S * 2) + s * 32;
                asm volatile("ldmatrix.sync.aligned.m8n8.x4.shared.b16 {%0,%1,%2,%3},[%4];"
                    : "=r"(a[mf][0]), "=r"(a[mf][1]), "=r"(a[mf][2]), "=r"(a[mf][3])
                    : "r"(addr));
            }
            uint32_t bf[8][2];
            #pragma unroll
            for (int nq = 0; nq < 4; ++nq) {
                uint32_t addr = b_lm + bufo + s * (16 * LDB_S * 2) + nq * 32;
                uint32_t r0, r1, r2, r3;
                asm volatile("ldmatrix.sync.aligned.m8n8.x4.trans.shared.b16 {%0,%1,%2,%3},[%4];"
                    : "=r"(r0), "=r"(r1), "=r"(r2), "=r"(r3) : "r"(addr));
                bf[nq * 2][0] = r0; bf[nq * 2][1] = r1;
                bf[nq * 2 + 1][0] = r2; bf[nq * 2 + 1][1] = r3;
            }
            #pragma unroll
            for (int mf = 0; mf < 4; ++mf)
                #pragma unroll
                for (int nf = 0; nf < 8; ++nf)
                    asm volatile(
                        "mma.sync.aligned.m16n8k16.row.col.f32.bf16.bf16.f32 "
                        "{%0,%1,%2,%3},{%4,%5,%6,%7},{%8,%9},{%0,%1,%2,%3};"
                        : "+f"(c[mf][nf][0]), "+f"(c[mf][nf][1]),
                          "+f"(c[mf][nf][2]), "+f"(c[mf][nf][3])
                        : "r"(a[mf][0]), "r"(a[mf][1]), "r"(a[mf][2]), "r"(a[mf][3]),
                          "r"(bf[nf][0]), "r"(bf[nf][1]));
        }
    }

    // ------------------------------ epilogue ----------------------------------
    const int gr = bm + warp_m + (lane >> 2);
    const int gc = bn + warp_n + (lane & 3) * 2;
    #pragma unroll
    for (int mf = 0; mf < 4; ++mf)
    #pragma unroll
    for (int nf = 0; nf < 8; ++nf)
    #pragma unroll
    for (int e = 0; e < 4; ++e) {
        const int row = gr + mf * 16 + ((e >> 1) << 3);
        const int col = gc + nf * 8 + (e & 1);
        const float acc = c[mf][nf][e];
        if constexpr (EPI == 0) {
            float zf = acc + p0[col];
            float sv = zf / (1.0f + __expf(-zf));
            if (col < H_) g_v[(size_t)row * H_ + col] = __float2bfloat16(sv);
            else          g_gate[(size_t)row * H_ + (col - H_)] = __float2bfloat16(sv);
        } else if constexpr (EPI == 1) {
            float zf = acc + p0[col];
            float sv = zf / (1.0f + __expf(-zf));
            float qv = sv * p1[col]       + p2[col];
            float kv = sv * p1[QK_ + col] + p2[QK_ + col];
            g_q[(size_t)row * QK_ + col] = __float2bfloat16(qv);
            int bb = row >> 12;
            int ii = row & (S_ - 1);
            g_kT[((size_t)bb * QK_ + col) * S_ + ii] = __float2bfloat16(kv);
        } else if constexpr (EPI == 2) {
            float bias = g_bias_lut[col - row + (S_ - 1)];
            float t = (acc + bias) * (1.0f / (float)S_);
            t = fmaxf(t, 0.0f);
            g_attn[((size_t)z * S_ + row) * S_ + col] = __float2bfloat16(t * t);
        } else if constexpr (EPI == 3) {
            size_t mg = (size_t)z * S_ + row;
            float gv = __bfloat162float(g_gate[mg * H_ + col]);
            g_og[mg * H_ + col] = __float2bfloat16(acc * gv);
        } else {
            size_t idx = (size_t)row * D_ + col;
            pout[idx] = acc + p0[col] + p1[idx];
        }
    }
}

// ------------------------------- launch ---------------------------------------
extern "C" void kernel_launch(void* const* d_in, const int* in_sizes, int n_in,
                              void* d_out, int out_size)
{
    const float* x    = (const float*)d_in[0];
    const float* ln_g = (const float*)d_in[1];
    const float* ln_b = (const float*)d_in[2];
    const float* Wh   = (const float*)d_in[3];
    const float* bh   = (const float*)d_in[4];
    const float* Wqk  = (const float*)d_in[5];
    const float* bqk  = (const float*)d_in[6];
    const float* osg  = (const float*)d_in[7];
    const float* osb  = (const float*)d_in[8];
    const float* Wo   = (const float*)d_in[9];
    const float* bo   = (const float*)d_in[10];
    const float* rel  = (const float*)d_in[11];
    float* out = (float*)d_out;

    static bool attr_done = false;
    if (!attr_done) {
        cudaFuncSetAttribute(gemm4<0, D_, 2 * H_>, cudaFuncAttributeMaxDynamicSharedMemorySize, SMEM_B);
        cudaFuncSetAttribute(gemm4<1, D_, QK_>,    cudaFuncAttributeMaxDynamicSharedMemorySize, SMEM_B);
        cudaFuncSetAttribute(gemm4<2, QK_, S_>,    cudaFuncAttributeMaxDynamicSharedMemorySize, SMEM_B);
        cudaFuncSetAttribute(gemm4<3, S_, H_>,     cudaFuncAttributeMaxDynamicSharedMemorySize, SMEM_B);
        cudaFuncSetAttribute(gemm4<4, H_, D_>,     cudaFuncAttributeMaxDynamicSharedMemorySize, SMEM_B);
        attr_done = true;
    }

    const int prep_total = D_ * 2 * H_ + D_ * QK_ + H_ * D_ + (2 * S_ - 1);
    prep_kernel<<<(prep_total + 255) / 256, 256>>>(Wh, Wqk, Wo, rel);
    ln_kernel<<<NBROWS, 256>>>(x, ln_g, ln_b);

    // hidden = silu(normed @ Wh + bh) -> v, gate
    gemm4<0, D_, 2 * H_><<<dim3((2 * H_) / BN, NBROWS / BM), 128, SMEM_B>>>(bh, nullptr, nullptr, nullptr);
    // qk = silu(normed @ Wqk + bqk) -> q, kT
    gemm4<1, D_, QK_><<<dim3(1, NBROWS / BM), 128, SMEM_B>>>(bqk, osg, osb, nullptr);
    // attn = relu((q kT + bias)/S)^2  (per batch)
    gemm4<2, QK_, S_><<<dim3(S_ / BN, S_ / BM, B_), 128, SMEM_B>>>(nullptr, nullptr, nullptr, nullptr);
    // og = (attn @ v) * gate  (per batch)
    gemm4<3, S_, H_><<<dim3(H_ / BN, S_ / BM, B_), 128, SMEM_B>>>(nullptr, nullptr, nullptr, nullptr);
    // out = og @ Wo + bo + x
    gemm4<4, H_, D_><<<dim3(D_ / BN, NBROWS / BM), 128, SMEM_B>>>(bo, x, nullptr, out);
}

// round 5
// speedup vs baseline: 1.4483x; 1.1879x over previous
#include <cuda_runtime.h>
#include <cuda_bf16.h>
#include <cstdint>
#include <cstddef>

// Problem dims (fixed)
#define B_   4
#define S_   4096
#define D_   1024
#define QK_  128
#define H_   2048
#define NBROWS (B_ * S_)   // 16384

// ------------------------- device scratch (static, no allocation) -------------
__device__ __nv_bfloat16 g_normed[(size_t)NBROWS * D_];
__device__ __nv_bfloat16 g_Wh [(size_t)D_ * 2 * H_];
__device__ __nv_bfloat16 g_Wqk[(size_t)D_ * QK_];
__device__ __nv_bfloat16 g_Wo [(size_t)H_ * D_];
__device__ __nv_bfloat16 g_v   [(size_t)NBROWS * H_];
__device__ __nv_bfloat16 g_gate[(size_t)NBROWS * H_];
__device__ __nv_bfloat16 g_q   [(size_t)NBROWS * QK_];
__device__ __nv_bfloat16 g_kT  [(size_t)B_ * QK_ * S_];
__device__ __nv_bfloat16 g_attn[(size_t)B_ * S_ * S_];
__device__ __nv_bfloat16 g_og  [(size_t)NBROWS * H_];
__device__ float g_bias_lut[2 * S_ - 1];
// per-128x128-tile "has any nonzero" mask of attn: [b][mtile][ktile]
__device__ unsigned char g_tmask[(size_t)B_ * 32 * 32];

// ------------------------- prep: weight conversion + rel-bias LUT -------------
__global__ void prep_kernel(const float* __restrict__ Wh,
                            const float* __restrict__ Wqk,
                            const float* __restrict__ Wo,
                            const float* __restrict__ rel_emb)
{
    int i = blockIdx.x * blockDim.x + threadIdx.x;
    const int nWh  = D_ * 2 * H_;
    const int nWqk = D_ * QK_;
    const int nWo  = H_ * D_;
    if (i < nWh) { g_Wh[i] = __float2bfloat16(Wh[i]); return; }
    i -= nWh;
    if (i < nWqk) { g_Wqk[i] = __float2bfloat16(Wqk[i]); return; }
    i -= nWqk;
    if (i < nWo) { g_Wo[i] = __float2bfloat16(Wo[i]); return; }
    i -= nWo;
    if (i < 2 * S_ - 1) {
        int d = i - (S_ - 1);
        int n = -d;
        int ret = (n < 0) ? 16 : 0;
        int na = n < 0 ? -n : n;
        int b;
        if (na < 8) b = na;
        else {
            float v = logf((float)na / 8.0f) / logf(16.0f) * 8.0f;
            int vi = 8 + (int)v;
            b = vi < 15 ? vi : 15;
        }
        g_bias_lut[i] = rel_emb[ret + b] * 32.0f;  // scale = sqrt(D)
    }
}

// ------------------------- LayerNorm: x -> normed (bf16) ----------------------
__global__ void ln_kernel(const float* __restrict__ x,
                          const float* __restrict__ gamma,
                          const float* __restrict__ beta)
{
    int row = blockIdx.x;
    const float4* xr = reinterpret_cast<const float4*>(x + (size_t)row * D_);
    float4 v = xr[threadIdx.x];
    float s  = v.x + v.y + v.z + v.w;
    float ss = fmaf(v.x, v.x, fmaf(v.y, v.y, fmaf(v.z, v.z, v.w * v.w)));
    #pragma unroll
    for (int o = 16; o; o >>= 1) {
        s  += __shfl_xor_sync(0xFFFFFFFFu, s,  o);
        ss += __shfl_xor_sync(0xFFFFFFFFu, ss, o);
    }
    __shared__ float sh[2][8];
    int lane = threadIdx.x & 31, w = threadIdx.x >> 5;
    if (lane == 0) { sh[0][w] = s; sh[1][w] = ss; }
    __syncthreads();
    if (threadIdx.x < 32) {
        float a = (threadIdx.x < 8) ? sh[0][threadIdx.x] : 0.f;
        float b = (threadIdx.x < 8) ? sh[1][threadIdx.x] : 0.f;
        #pragma unroll
        for (int o = 4; o; o >>= 1) {
            a += __shfl_xor_sync(0xFFFFFFFFu, a, o);
            b += __shfl_xor_sync(0xFFFFFFFFu, b, o);
        }
        if (threadIdx.x == 0) { sh[0][0] = a; sh[1][0] = b; }
    }
    __syncthreads();
    float mean = sh[0][0] * (1.0f / D_);
    float var  = sh[1][0] * (1.0f / D_) - mean * mean;
    float r = rsqrtf(var + 1e-5f);
    int c = threadIdx.x * 4;
    __nv_bfloat16* o = g_normed + (size_t)row * D_;
    o[c + 0] = __float2bfloat16((v.x - mean) * r * gamma[c + 0] + beta[c + 0]);
    o[c + 1] = __float2bfloat16((v.y - mean) * r * gamma[c + 1] + beta[c + 1]);
    o[c + 2] = __float2bfloat16((v.z - mean) * r * gamma[c + 2] + beta[c + 2]);
    o[c + 3] = __float2bfloat16((v.w - mean) * r * gamma[c + 3] + beta[c + 3]);
}

// ------------------------- generic bf16 tensor-core GEMM ----------------------
// CTA tile 128x128, 4 warps (128 thr), warp tile 64x64, 4-stage cp.async.
#define BM 128
#define BN 128
#define BK 32
#define NSTAGE 4
#define LDA_S 40    // elements (80 B pitch)  -> conflict-free ldmatrix
#define LDB_S 136   // elements (272 B pitch)
#define ASTAGE_B (BM * LDA_S * 2)          // 10240
#define BSTAGE_B (BK * LDB_S * 2)          // 8704
#define STAGE_B  (ASTAGE_B + BSTAGE_B)     // 18944
#define SMEM_B   (NSTAGE * STAGE_B)        // 75776

__device__ __forceinline__ uint32_t s2u(const void* p) {
    return (uint32_t)__cvta_generic_to_shared(p);
}
#define CP16(dst, src) \
    asm volatile("cp.async.cg.shared.global [%0], [%1], 16;\n" :: "r"(dst), "l"(src))

// EPI: 0=hidden(silu->v/gate) 1=qk(silu->q,kT) 2=sim(bias,relu^2->attn + tile mask)
//      3=av(*gate->og, mask-skip) 4=out(+bo+x->f32)
template<int EPI, int Kc, int Nc>
__global__ void __launch_bounds__(128, 2)
gemm4(const float* __restrict__ p0, const float* __restrict__ p1,
      const float* __restrict__ p2, float* __restrict__ pout)
{
    extern __shared__ unsigned char smraw[];
    const uint32_t smu = s2u(smraw);
    __shared__ int s_list[128];
    __shared__ int s_cnt;
    __shared__ int s_any;

    const int tid  = threadIdx.x;
    const int lane = tid & 31;
    const int warp = tid >> 5;
    const int warp_m = (warp >> 1) * 64;
    const int warp_n = (warp & 1) * 64;
    const int bm = blockIdx.y * BM;
    const int bn = blockIdx.x * BN;
    const int z  = blockIdx.z;

    const __nv_bfloat16 *A, *Bg;
    if constexpr (EPI == 0)      { A = g_normed; Bg = g_Wh; }
    else if constexpr (EPI == 1) { A = g_normed; Bg = g_Wqk; }
    else if constexpr (EPI == 2) { A = g_q   + (size_t)z * S_ * QK_;
                                   Bg = g_kT + (size_t)z * QK_ * S_; }
    else if constexpr (EPI == 3) { A = g_attn + (size_t)z * S_ * S_;
                                   Bg = g_v   + (size_t)z * S_ * H_; }
    else                         { A = g_og; Bg = g_Wo; }

    const int KT = Kc / BK;

    // Active k-slab list (EPI==3 consults the attn tile mask; others: identity).
    int n_slabs;
    if constexpr (EPI == 3) {
        if (tid == 0) {
            const unsigned char* mrow = g_tmask + (size_t)z * 1024 + (bm >> 7) * 32;
            int c = 0;
            for (int t = 0; t < 32; ++t)
                if (mrow[t]) {
                    s_list[c]     = t * 4;
                    s_list[c + 1] = t * 4 + 1;
                    s_list[c + 2] = t * 4 + 2;
                    s_list[c + 3] = t * 4 + 3;
                    c += 4;
                }
            s_cnt = c;
        }
        __syncthreads();
        n_slabs = s_cnt;
    } else {
        n_slabs = KT;
    }

    // gmem->smem tiling: A 128x32 (512 x16B chunks), B 32x128 (512 chunks), 128 thr
    const int arow = tid >> 2;            // 0..31 (+32*i)
    const int acol = (tid & 3) * 8;       // k offset (elems)
    const int brow = tid >> 4;            // 0..7 (+8*i)
    const int bcol = (tid & 15) * 8;      // n offset (elems)

    const __nv_bfloat16* a_src = A  + (size_t)(bm + arow) * Kc + acol;
    const __nv_bfloat16* b_src = Bg + (size_t)brow * Nc + bn + bcol;
    const uint32_t a_dst = smu + arow * (LDA_S * 2) + acol * 2;
    const uint32_t b_dst = smu + ASTAGE_B + brow * (LDB_S * 2) + bcol * 2;

    // ldmatrix per-lane addressing
    const int q8    = lane >> 3;
    const int lrow  = (lane & 7) + (q8 & 1) * 8;
    const int lcol8 = (q8 >> 1) * 8;
    const uint32_t a_lm = smu + (warp_m + lrow) * (LDA_S * 2) + lcol8 * 2;
    const uint32_t b_lm = smu + ASTAGE_B + lrow * (LDB_S * 2) + (warp_n + lcol8) * 2;

    // prologue: stages 0..NSTAGE-2
    #pragma unroll
    for (int s = 0; s < NSTAGE - 1; ++s) {
        if (s < n_slabs) {
            const int ks = (EPI == 3) ? s_list[s] : s;
            const uint32_t so = s * STAGE_B;
            #pragma unroll
            for (int i = 0; i < 4; ++i)
                CP16(a_dst + so + i * 32 * (LDA_S * 2),
                     a_src + (size_t)ks * BK + (size_t)i * 32 * Kc);
            #pragma unroll
            for (int i = 0; i < 4; ++i)
                CP16(b_dst + so + i * 8 * (LDB_S * 2),
                     b_src + (size_t)ks * BK * Nc + (size_t)i * 8 * Nc);
        }
        asm volatile("cp.async.commit_group;\n");
    }

    float c[4][8][4] = {};

    for (int it = 0; it < n_slabs; ++it) {
        asm volatile("cp.async.wait_group %0;\n" :: "n"(NSTAGE - 2));
        __syncthreads();
        {
            const int pf = it + NSTAGE - 1;
            if (pf < n_slabs) {
                const int ks = (EPI == 3) ? s_list[pf] : pf;
                const uint32_t so = (pf % NSTAGE) * STAGE_B;
                #pragma unroll
                for (int i = 0; i < 4; ++i)
                    CP16(a_dst + so + i * 32 * (LDA_S * 2),
                         a_src + (size_t)ks * BK + (size_t)i * 32 * Kc);
                #pragma unroll
                for (int i = 0; i < 4; ++i)
                    CP16(b_dst + so + i * 8 * (LDB_S * 2),
                         b_src + (size_t)ks * BK * Nc + (size_t)i * 8 * Nc);
            }
            asm volatile("cp.async.commit_group;\n");
        }
        const uint32_t bufo = (it % NSTAGE) * STAGE_B;
        #pragma unroll
        for (int s = 0; s < 2; ++s) {          // two k16 steps per BK
            uint32_t a[4][4];
            #pragma unroll
            for (int mf = 0; mf < 4; ++mf) {
                uint32_t addr = a_lm + bufo + mf * (16 * LDA_S * 2) + s * 32;
                asm volatile("ldmatrix.sync.aligned.m8n8.x4.shared.b16 {%0,%1,%2,%3},[%4];"
                    : "=r"(a[mf][0]), "=r"(a[mf][1]), "=r"(a[mf][2]), "=r"(a[mf][3])
                    : "r"(addr));
            }
            uint32_t bf[8][2];
            #pragma unroll
            for (int nq = 0; nq < 4; ++nq) {
                uint32_t addr = b_lm + bufo + s * (16 * LDB_S * 2) + nq * 32;
                uint32_t r0, r1, r2, r3;
                asm volatile("ldmatrix.sync.aligned.m8n8.x4.trans.shared.b16 {%0,%1,%2,%3},[%4];"
                    : "=r"(r0), "=r"(r1), "=r"(r2), "=r"(r3) : "r"(addr));
                bf[nq * 2][0] = r0; bf[nq * 2][1] = r1;
                bf[nq * 2 + 1][0] = r2; bf[nq * 2 + 1][1] = r3;
            }
            #pragma unroll
            for (int mf = 0; mf < 4; ++mf)
                #pragma unroll
                for (int nf = 0; nf < 8; ++nf)
                    asm volatile(
                        "mma.sync.aligned.m16n8k16.row.col.f32.bf16.bf16.f32 "
                        "{%0,%1,%2,%3},{%4,%5,%6,%7},{%8,%9},{%0,%1,%2,%3};"
                        : "+f"(c[mf][nf][0]), "+f"(c[mf][nf][1]),
                          "+f"(c[mf][nf][2]), "+f"(c[mf][nf][3])
                        : "r"(a[mf][0]), "r"(a[mf][1]), "r"(a[mf][2]), "r"(a[mf][3]),
                          "r"(bf[nf][0]), "r"(bf[nf][1]));
        }
    }

    // ------------------------------ epilogue ----------------------------------
    const int gr = bm + warp_m + (lane >> 2);
    const int gc = bn + warp_n + (lane & 3) * 2;

    if constexpr (EPI == 2) {
        // pass 1: relu^2 values + tile-activity flag (exact)
        float t2[4][8][4];
        bool any = false;
        #pragma unroll
        for (int mf = 0; mf < 4; ++mf)
        #pragma unroll
        for (int nf = 0; nf < 8; ++nf)
        #pragma unroll
        for (int e = 0; e < 4; ++e) {
            const int row = gr + mf * 16 + ((e >> 1) << 3);
            const int col = gc + nf * 8 + (e & 1);
            float bias = g_bias_lut[col - row + (S_ - 1)];
            float t = (c[mf][nf][e] + bias) * (1.0f / (float)S_);
            t = fmaxf(t, 0.0f);
            any = any || (t > 0.0f);
            t2[mf][nf][e] = t * t;
        }
        if (tid == 0) s_any = 0;
        __syncthreads();
        if (any) s_any = 1;
        __syncthreads();
        if (tid == 0)
            g_tmask[(size_t)z * 1024 + (bm >> 7) * 32 + (bn >> 7)] =
                (unsigned char)s_any;
        if (s_any) {
            #pragma unroll
            for (int mf = 0; mf < 4; ++mf)
            #pragma unroll
            for (int nf = 0; nf < 8; ++nf)
            #pragma unroll
            for (int e = 0; e < 4; ++e) {
                const int row = gr + mf * 16 + ((e >> 1) << 3);
                const int col = gc + nf * 8 + (e & 1);
                g_attn[((size_t)z * S_ + row) * S_ + col] =
                    __float2bfloat16(t2[mf][nf][e]);
            }
        }
    } else {
        #pragma unroll
        for (int mf = 0; mf < 4; ++mf)
        #pragma unroll
        for (int nf = 0; nf < 8; ++nf)
        #pragma unroll
        for (int e = 0; e < 4; ++e) {
            const int row = gr + mf * 16 + ((e >> 1) << 3);
            const int col = gc + nf * 8 + (e & 1);
            const float acc = c[mf][nf][e];
            if constexpr (EPI == 0) {
                float zf = acc + p0[col];
                float sv = zf / (1.0f + __expf(-zf));
                if (col < H_) g_v[(size_t)row * H_ + col] = __float2bfloat16(sv);
                else          g_gate[(size_t)row * H_ + (col - H_)] = __float2bfloat16(sv);
            } else if constexpr (EPI == 1) {
                float zf = acc + p0[col];
                float sv = zf / (1.0f + __expf(-zf));
                float qv = sv * p1[col]       + p2[col];
                float kv = sv * p1[QK_ + col] + p2[QK_ + col];
                g_q[(size_t)row * QK_ + col] = __float2bfloat16(qv);
                int bb = row >> 12;
                int ii = row & (S_ - 1);
                g_kT[((size_t)bb * QK_ + col) * S_ + ii] = __float2bfloat16(kv);
            } else if constexpr (EPI == 3) {
                size_t mg = (size_t)z * S_ + row;
                float gv = __bfloat162float(g_gate[mg * H_ + col]);
                g_og[mg * H_ + col] = __float2bfloat16(acc * gv);
            } else {
                size_t idx = (size_t)row * D_ + col;
                pout[idx] = acc + p0[col] + p1[idx];
            }
        }
    }
}

// ------------------------------- launch ---------------------------------------
extern "C" void kernel_launch(void* const* d_in, const int* in_sizes, int n_in,
                              void* d_out, int out_size)
{
    const float* x    = (const float*)d_in[0];
    const float* ln_g = (const float*)d_in[1];
    const float* ln_b = (const float*)d_in[2];
    const float* Wh   = (const float*)d_in[3];
    const float* bh   = (const float*)d_in[4];
    const float* Wqk  = (const float*)d_in[5];
    const float* bqk  = (const float*)d_in[6];
    const float* osg  = (const float*)d_in[7];
    const float* osb  = (const float*)d_in[8];
    const float* Wo   = (const float*)d_in[9];
    const float* bo   = (const float*)d_in[10];
    const float* rel  = (const float*)d_in[11];
    float* out = (float*)d_out;

    static bool attr_done = false;
    if (!attr_done) {
        cudaFuncSetAttribute(gemm4<0, D_, 2 * H_>, cudaFuncAttributeMaxDynamicSharedMemorySize, SMEM_B);
        cudaFuncSetAttribute(gemm4<1, D_, QK_>,    cudaFuncAttributeMaxDynamicSharedMemorySize, SMEM_B);
        cudaFuncSetAttribute(gemm4<2, QK_, S_>,    cudaFuncAttributeMaxDynamicSharedMemorySize, SMEM_B);
        cudaFuncSetAttribute(gemm4<3, S_, H_>,     cudaFuncAttributeMaxDynamicSharedMemorySize, SMEM_B);
        cudaFuncSetAttribute(gemm4<4, H_, D_>,     cudaFuncAttributeMaxDynamicSharedMemorySize, SMEM_B);
        attr_done = true;
    }

    const int prep_total = D_ * 2 * H_ + D_ * QK_ + H_ * D_ + (2 * S_ - 1);
    prep_kernel<<<(prep_total + 255) / 256, 256>>>(Wh, Wqk, Wo, rel);
    ln_kernel<<<NBROWS, 256>>>(x, ln_g, ln_b);

    // hidden = silu(normed @ Wh + bh) -> v, gate
    gemm4<0, D_, 2 * H_><<<dim3((2 * H_) / BN, NBROWS / BM), 128, SMEM_B>>>(bh, nullptr, nullptr, nullptr);
    // qk = silu(normed @ Wqk + bqk) -> q, kT
    gemm4<1, D_, QK_><<<dim3(1, NBROWS / BM), 128, SMEM_B>>>(bqk, osg, osb, nullptr);
    // attn = relu((q kT + bias)/S)^2  (per batch) + exact tile mask
    gemm4<2, QK_, S_><<<dim3(S_ / BN, S_ / BM, B_), 128, SMEM_B>>>(nullptr, nullptr, nullptr, nullptr);
    // og = (attn @ v) * gate  (per batch; skips all-zero attn tiles)
    gemm4<3, S_, H_><<<dim3(H_ / BN, S_ / BM, B_), 128, SMEM_B>>>(nullptr, nullptr, nullptr, nullptr);
    // out = og @ Wo + bo + x
    gemm4<4, H_, D_><<<dim3(D_ / BN, NBROWS / BM), 128, SMEM_B>>>(bo, x, nullptr, out);
}